// round 1
// baseline (speedup 1.0000x reference)
#include <cuda_runtime.h>

#define NBLK 1024   // 256 batches * 4 row-chunks

// Per-block partial sums: [base, bc, cont, ns]. Fully rewritten every launch.
__device__ float g_part[NBLK][4];

__device__ __forceinline__ float g1x(const float* f, int i, float inv_h, float inv_2h) {
    if (i == 0)   return (f[1]   - f[0])   * inv_h;
    if (i == 125) return (f[125] - f[124]) * inv_h;
    return (f[i + 1] - f[i - 1]) * inv_2h;
}

__global__ __launch_bounds__(128) void physics_kernel(
    const float* __restrict__ inp,   // (256,1,128,128)
    const float* __restrict__ outp,  // (256,3,128,128)
    const float* __restrict__ tgt)   // (256,3,128,128)
{
    const int blk   = blockIdx.x;
    const int b     = blk >> 2;
    const int chunk = blk & 3;
    const int tx    = threadIdx.x;
    const int y0    = chunk * 32;

    const float INV_SX  = 127.0f / 1.2f;
    const float INV_2SX = 127.0f / 2.4f;
    const float INV_SY  = 127.0f / 0.8f;
    const float INV_2SY = 127.0f / 1.6f;

    const float* Ob = outp + b * 3 * 16384;
    const float* Tb = tgt  + b * 3 * 16384;
    const float* Ib = inp  + b * 16384;

    float s_base = 0.f, s_bc = 0.f, s_cont = 0.f, s_ns = 0.f;

    // ---------- base loss + boundary loss (stream 32 full rows) ----------
    for (int y = y0; y < y0 + 32; ++y) {
        float o0 = Ob[0 * 16384 + y * 128 + tx];
        float o1 = Ob[1 * 16384 + y * 128 + tx];
        float o2 = Ob[2 * 16384 + y * 128 + tx];
        float t0 = Tb[0 * 16384 + y * 128 + tx];
        float t1 = Tb[1 * 16384 + y * 128 + tx];
        float t2 = Tb[2 * 16384 + y * 128 + tx];
        float d0 = o0 - t0, d1 = o1 - t1, d2 = o2 - t2;
        s_base += d0 * d0 + d1 * d1 + d2 * d2;

        // boundary pieces (with exact multiplicity of the reference concat)
        if (y >= 55 && y < 73) {
            if (tx == 0)   { float e = o1 - 0.01f; s_bc += e * e; }
            if (tx == 127) { s_bc += o0 * o0; }
        }
        float m = 0.f;
        if (y == 0 || y == 127) m += 1.f;                              // full rows, ch 1&2
        if ((tx == 0 || tx == 127) && (y >= 73 || y < 55)) m += 1.f;   // columns, ch 1&2
        if (m > 0.f) s_bc += m * (o1 * o1 + o2 * o2);
    }

    // ---------- PDE part on cropped 126x126 interior ----------
    __shared__ float su[5][128];
    __shared__ float sv[5][128];
    __shared__ float sp[3][128];

    const int jlo = max(y0 - 1, 0);
    const int jhi = min(y0 + 31, 126);

    // prime ring buffers
    if (tx < 126) {
        int rlo = max(jlo - 2, 0), rhi = min(jlo + 2, 125);
        for (int r = rlo; r <= rhi; ++r) {
            su[r % 5][tx] = Ob[1 * 16384 + (r + 1) * 128 + tx + 1];
            sv[r % 5][tx] = Ob[2 * 16384 + (r + 1) * 128 + tx + 1];
        }
        int plo = max(jlo - 1, 0), phi = min(jlo + 1, 125);
        for (int r = plo; r <= phi; ++r)
            sp[r % 3][tx] = Ob[0 * 16384 + (r + 1) * 128 + tx + 1];
    }
    __syncthreads();

    for (int j = jlo; j < jhi; ++j) {
        if (tx < 126) {
            const int i = tx;
            const float* fu = su[j % 5];
            const float* fv = sv[j % 5];
            const float* fp = sp[j % 3];
            float u0 = fu[i], v0 = fv[i];

            // x-direction derivatives (torch.gradient semantics)
            float du_dx = g1x(fu, i, INV_SX, INV_2SX);
            float dv_dx = g1x(fv, i, INV_SX, INV_2SX);
            float dp_dx = g1x(fp, i, INV_SX, INV_2SX);
            float du_dxx, dv_dxx;
            if (i == 0) {
                du_dxx = (g1x(fu, 1, INV_SX, INV_2SX) - du_dx) * INV_SX;
                dv_dxx = (g1x(fv, 1, INV_SX, INV_2SX) - dv_dx) * INV_SX;
            } else if (i == 125) {
                du_dxx = (du_dx - g1x(fu, 124, INV_SX, INV_2SX)) * INV_SX;
                dv_dxx = (dv_dx - g1x(fv, 124, INV_SX, INV_2SX)) * INV_SX;
            } else {
                du_dxx = (g1x(fu, i + 1, INV_SX, INV_2SX) - g1x(fu, i - 1, INV_SX, INV_2SX)) * INV_2SX;
                dv_dxx = (g1x(fv, i + 1, INV_SX, INV_2SX) - g1x(fv, i - 1, INV_SX, INV_2SX)) * INV_2SX;
            }

            // y-direction derivatives via ring buffer
            auto UR = [&](int r) -> float { return su[r % 5][i]; };
            auto VR = [&](int r) -> float { return sv[r % 5][i]; };
            auto PR = [&](int r) -> float { return sp[r % 3][i]; };
            auto gyU = [&](int r) -> float {
                if (r == 0)   return (UR(1)   - UR(0))   * INV_SY;
                if (r == 125) return (UR(125) - UR(124)) * INV_SY;
                return (UR(r + 1) - UR(r - 1)) * INV_2SY;
            };
            auto gyV = [&](int r) -> float {
                if (r == 0)   return (VR(1)   - VR(0))   * INV_SY;
                if (r == 125) return (VR(125) - VR(124)) * INV_SY;
                return (VR(r + 1) - VR(r - 1)) * INV_2SY;
            };

            float du_dy = gyU(j), dv_dy = gyV(j);
            float dp_dy;
            if (j == 0)        dp_dy = (PR(1)   - PR(0))   * INV_SY;
            else if (j == 125) dp_dy = (PR(125) - PR(124)) * INV_SY;
            else               dp_dy = (PR(j + 1) - PR(j - 1)) * INV_2SY;

            float du_dyy, dv_dyy;
            if (j == 0) {
                du_dyy = (gyU(1) - du_dy) * INV_SY;
                dv_dyy = (gyV(1) - dv_dy) * INV_SY;
            } else if (j == 125) {
                du_dyy = (du_dy - gyU(124)) * INV_SY;
                dv_dyy = (dv_dy - gyV(124)) * INV_SY;
            } else {
                du_dyy = (gyU(j + 1) - gyU(j - 1)) * INV_2SY;
                dv_dyy = (gyV(j + 1) - gyV(j - 1)) * INV_2SY;
            }

            float alpha = Ib[(j + 1) * 128 + i + 1];

            float div = du_dx + dv_dy;
            s_cont += div * div;
            float xres = u0 * du_dx + v0 * du_dy + dp_dx - (du_dxx + du_dyy) + alpha * u0;
            float yres = u0 * dv_dx + v0 * dv_dy + dp_dy - (dv_dxx + dv_dyy) + alpha * v0;
            s_ns += xres * xres + yres * yres;
        }
        __syncthreads();
        // advance ring buffers
        if (j + 1 < jhi && tx < 126) {
            int ru = j + 3;
            if (ru <= 125) {
                su[ru % 5][tx] = Ob[1 * 16384 + (ru + 1) * 128 + tx + 1];
                sv[ru % 5][tx] = Ob[2 * 16384 + (ru + 1) * 128 + tx + 1];
            }
            int rp = j + 2;
            if (rp <= 125)
                sp[rp % 3][tx] = Ob[0 * 16384 + (rp + 1) * 128 + tx + 1];
        }
        __syncthreads();
    }

    // ---------- block reduction ----------
    float vals[4] = {s_base, s_bc, s_cont, s_ns};
    __shared__ float rbuf[4][4];
    int lane = tx & 31, wid = tx >> 5;
#pragma unroll
    for (int k = 0; k < 4; ++k) {
        float v = vals[k];
#pragma unroll
        for (int off = 16; off; off >>= 1) v += __shfl_down_sync(0xffffffffu, v, off);
        if (lane == 0) rbuf[k][wid] = v;
    }
    __syncthreads();
    if (tx == 0) {
#pragma unroll
        for (int k = 0; k < 4; ++k)
            g_part[blk][k] = rbuf[k][0] + rbuf[k][1] + rbuf[k][2] + rbuf[k][3];
    }
}

__global__ __launch_bounds__(NBLK) void finalize_kernel(float* __restrict__ out) {
    const int t = threadIdx.x;
    double v[4];
#pragma unroll
    for (int k = 0; k < 4; ++k) v[k] = (double)g_part[t][k];

    __shared__ double sred[4][32];
    int lane = t & 31, w = t >> 5;
#pragma unroll
    for (int k = 0; k < 4; ++k) {
        double x = v[k];
#pragma unroll
        for (int off = 16; off; off >>= 1) x += __shfl_down_sync(0xffffffffu, x, off);
        if (lane == 0) sred[k][w] = x;
    }
    __syncthreads();
    if (t == 0) {
        double tot[4];
#pragma unroll
        for (int k = 0; k < 4; ++k) {
            double s = 0.0;
            for (int i = 0; i < 32; ++i) s += sred[k][i];
            tot[k] = s;
        }
        const double NI = 256.0 * 126.0 * 126.0;
        double loss_base = tot[0] / 300000.0;
        double loss_bc   = tot[1] / (256.0 * 988.0);
        double loss_cont = (tot[2] / NI) / 1e-5;
        double loss_ns   = (tot[3] / (NI * 2.0)) / 0.01;
        double A_LOSS = 1.0 - 0.3 - 0.3 - 0.3;  // match python float arithmetic
        out[0] = (float)(A_LOSS * loss_base + 0.3 * loss_cont + 0.3 * loss_ns + 0.3 * loss_bc);
    }
}

extern "C" void kernel_launch(void* const* d_in, const int* in_sizes, int n_in,
                              void* d_out, int out_size) {
    // Identify inputs (the small tensor) vs outputs/targets (order-preserving)
    const int SMALL = 256 * 128 * 128;
    int idx_in = 0;
    for (int i = 0; i < n_in; ++i)
        if (in_sizes[i] == SMALL) { idx_in = i; break; }
    const float* inp = (const float*)d_in[idx_in];
    const float* big[2];
    int nb = 0;
    for (int i = 0; i < n_in && nb < 2; ++i)
        if (i != idx_in) big[nb++] = (const float*)d_in[i];
    const float* outp = big[0];
    const float* tgt  = big[1];

    physics_kernel<<<NBLK, 128>>>(inp, outp, tgt);
    finalize_kernel<<<1, NBLK>>>((float*)d_out);
}

// round 2
// speedup vs baseline: 1.4000x; 1.4000x over previous
#include <cuda_runtime.h>

#define NBLK 1024   // 256 batches * 4 row-chunks

__device__ float g_part[NBLK][4];
__device__ unsigned int g_ctr;

// 1st+2nd derivative with torch.gradient semantics on a cropped 126-array.
// cls: 0=left edge, 1=left+1, 2=interior, 3=right-1, 4=right edge
__device__ __forceinline__ void d12(float fm2, float fm1, float f0, float fp1, float fp2,
                                    int cls, float inv_h, float inv_2h, float c2,
                                    float& d1, float& d2) {
    if (cls == 2)      { d1 = (fp1 - fm1) * inv_2h; d2 = (fp2 - 2.f * f0 + fm2) * c2; }
    else if (cls == 0) { d1 = (fp1 - f0) * inv_h;
                         d2 = ((fp2 - f0) * inv_2h - (fp1 - f0) * inv_h) * inv_h; }
    else if (cls == 1) { d1 = (fp1 - fm1) * inv_2h;
                         d2 = ((fp2 - f0) * inv_2h - (f0 - fm1) * inv_h) * inv_2h; }
    else if (cls == 3) { d1 = (fp1 - fm1) * inv_2h;
                         d2 = ((fp1 - f0) * inv_h - (f0 - fm2) * inv_2h) * inv_2h; }
    else               { d1 = (f0 - fm1) * inv_h;
                         d2 = ((f0 - fm1) * inv_h - (f0 - fm2) * inv_2h) * inv_h; }
}

__global__ __launch_bounds__(128) void physics_kernel(
    const float* __restrict__ inp,   // (256,1,128,128)
    const float* __restrict__ outp,  // (256,3,128,128)
    const float* __restrict__ tgt,   // (256,3,128,128)
    float* __restrict__ out)
{
    const int blk   = blockIdx.x;
    const int b     = blk >> 2;
    const int chunk = blk & 3;
    const int tx    = threadIdx.x;
    const int y0    = chunk * 32;

    constexpr float INV_SX  = 127.0f / 1.2f;
    constexpr float INV_2SX = 127.0f / 2.4f;
    constexpr float INV_SY  = 127.0f / 0.8f;
    constexpr float INV_2SY = 127.0f / 1.6f;
    constexpr float C2X = INV_2SX * INV_2SX;
    constexpr float C2Y = INV_2SY * INV_2SY;

    const float* Ob = outp + b * 49152;
    const float* Tb = tgt  + b * 49152;
    const float* Ib = inp  + b * 16384;

    float s_base = 0.f, s_bc = 0.f, s_cont = 0.f, s_ns = 0.f;

    // ---------------- base loss + boundary loss (float4, 4 rows/iter) ----------------
    {
        const float4* O4 = (const float4*)Ob;
        const float4* T4 = (const float4*)Tb;
        const int col4 = tx & 31;
        const int ry   = tx >> 5;
#pragma unroll
        for (int it = 0; it < 8; ++it) {
            int y   = y0 + it * 4 + ry;
            int idx = y * 32 + col4;
            float4 o0 = O4[idx], o1 = O4[4096 + idx], o2 = O4[8192 + idx];
            float4 t0 = T4[idx], t1 = T4[4096 + idx], t2 = T4[8192 + idx];
            float d;
            d = o0.x - t0.x; s_base += d * d;  d = o0.y - t0.y; s_base += d * d;
            d = o0.z - t0.z; s_base += d * d;  d = o0.w - t0.w; s_base += d * d;
            d = o1.x - t1.x; s_base += d * d;  d = o1.y - t1.y; s_base += d * d;
            d = o1.z - t1.z; s_base += d * d;  d = o1.w - t1.w; s_base += d * d;
            d = o2.x - t2.x; s_base += d * d;  d = o2.y - t2.y; s_base += d * d;
            d = o2.z - t2.z; s_base += d * d;  d = o2.w - t2.w; s_base += d * d;

            bool midrow = (y >= 55) && (y < 73);
            if (y == 0 || y == 127)
                s_bc += o1.x * o1.x + o1.y * o1.y + o1.z * o1.z + o1.w * o1.w
                      + o2.x * o2.x + o2.y * o2.y + o2.z * o2.z + o2.w * o2.w;
            if (col4 == 0) {
                if (midrow) { float e = o1.x - 0.01f; s_bc += e * e; }
                else        s_bc += o1.x * o1.x + o2.x * o2.x;
            }
            if (col4 == 31) {
                if (midrow) s_bc += o0.w * o0.w;
                else        s_bc += o1.w * o1.w + o2.w * o2.w;
            }
        }
    }

    // ---------------- PDE on cropped 126x126 interior ----------------
    // Cropped coords (r,i) map to global (r+1, i+1).
    __shared__ float2 suv[6][128];   // {u,v}, ring depth 6
    __shared__ float  sp [4][128];   // p, ring depth 4

    const float* U = Ob + 16384 + 129;   // U[r*128 + i]
    const float* V = Ob + 32768 + 129;
    const float* P = Ob + 129;
    const float* A = Ib + 129;

    const int jlo = max(y0 - 1, 0);
    const int jhi = min(y0 + 31, 126);
    const bool act = (tx < 126);

    // prologue: rows jlo-2..jlo+1 of u,v; rows jlo-1..jlo of p
    if (act) {
        for (int r = max(jlo - 2, 0); r <= jlo + 1; ++r)
            suv[r % 6][tx] = make_float2(U[r * 128 + tx], V[r * 128 + tx]);
        for (int r = max(jlo - 1, 0); r <= jlo; ++r)
            sp[r % 4][tx] = P[r * 128 + tx];
    }
    // prefetch row jlo+2 (uv), jlo+1 (p)
    float pu = 0.f, pv = 0.f, pp = 0.f;
    if (act) {
        int ru = jlo + 2; if (ru <= 125) { pu = U[ru * 128 + tx]; pv = V[ru * 128 + tx]; }
        int rp = jlo + 1; if (rp <= 125) { pp = P[rp * 128 + tx]; }
    }
    __syncthreads();

    for (int j = jlo; j < jhi; ++j) {
        // store prefetched rows (row j+2 uv, row j+1 p)
        if (act) {
            int ru = j + 2; if (ru <= 125) suv[ru % 6][tx] = make_float2(pu, pv);
            int rp = j + 1; if (rp <= 125) sp[rp % 4][tx] = pp;
        }
        __syncthreads();

        if (act) {
            const int i = tx;
            const float2* r_c = suv[j % 6];
            const float*  p_c = sp[j % 4];

            float2 c = r_c[i];

            // x-direction
            float2 xm2 = r_c[max(i - 2, 0)],  xm1 = r_c[max(i - 1, 0)];
            float2 xp1 = r_c[min(i + 1, 125)], xp2 = r_c[min(i + 2, 125)];
            int cls_x = (i >= 2 && i <= 123) ? 2 : (i == 0 ? 0 : (i == 1 ? 1 : (i == 124 ? 3 : 4)));
            float du_dx, du_dxx, dv_dx, dv_dxx;
            d12(xm2.x, xm1.x, c.x, xp1.x, xp2.x, cls_x, INV_SX, INV_2SX, C2X, du_dx, du_dxx);
            d12(xm2.y, xm1.y, c.y, xp1.y, xp2.y, cls_x, INV_SX, INV_2SX, C2X, dv_dx, dv_dxx);

            float pc  = p_c[i];
            float pxm = p_c[max(i - 1, 0)], pxp = p_c[min(i + 1, 125)];
            float dp_dx = (i == 0)   ? (pxp - pc) * INV_SX
                        : (i == 125) ? (pc - pxm) * INV_SX
                                     : (pxp - pxm) * INV_2SX;

            // y-direction (ring slots for clamped rows are resident)
            float2 ym2 = suv[max(j - 2, 0) % 6][i];
            float2 ym1 = suv[max(j - 1, 0) % 6][i];
            float2 yp1 = suv[min(j + 1, 125) % 6][i];
            float2 yp2 = suv[min(j + 2, 125) % 6][i];
            int cls_y = (j >= 2 && j <= 123) ? 2 : (j == 0 ? 0 : (j == 1 ? 1 : (j == 124 ? 3 : 4)));
            float du_dy, du_dyy, dv_dy, dv_dyy;
            d12(ym2.x, ym1.x, c.x, yp1.x, yp2.x, cls_y, INV_SY, INV_2SY, C2Y, du_dy, du_dyy);
            d12(ym2.y, ym1.y, c.y, yp1.y, yp2.y, cls_y, INV_SY, INV_2SY, C2Y, dv_dy, dv_dyy);

            float pym = sp[max(j - 1, 0) % 4][i];
            float pyp = sp[min(j + 1, 125) % 4][i];
            float dp_dy = (j == 0)   ? (pyp - pc) * INV_SY
                        : (j == 125) ? (pc - pym) * INV_SY
                                     : (pyp - pym) * INV_2SY;

            float alpha = A[j * 128 + i];

            float div = du_dx + dv_dy;
            s_cont += div * div;
            float xres = c.x * du_dx + c.y * du_dy + dp_dx - (du_dxx + du_dyy) + alpha * c.x;
            float yres = c.x * dv_dx + c.y * dv_dy + dp_dy - (dv_dxx + dv_dyy) + alpha * c.y;
            s_ns += xres * xres + yres * yres;
        }

        // prefetch next rows (row j+3 uv, row j+2 p)
        if (act) {
            int ru = j + 3; if (ru <= 125) { pu = U[ru * 128 + tx]; pv = V[ru * 128 + tx]; }
            int rp = j + 2; if (rp <= 125) { pp = P[rp * 128 + tx]; }
        }
    }

    // ---------------- block reduction -> g_part ----------------
    {
        float vals[4] = {s_base, s_bc, s_cont, s_ns};
        __shared__ float rbuf[4][4];
        int lane = tx & 31, wid = tx >> 5;
#pragma unroll
        for (int k = 0; k < 4; ++k) {
            float v = vals[k];
#pragma unroll
            for (int off = 16; off; off >>= 1) v += __shfl_down_sync(0xffffffffu, v, off);
            if (lane == 0) rbuf[k][wid] = v;
        }
        __syncthreads();
        if (tx == 0) {
#pragma unroll
            for (int k = 0; k < 4; ++k)
                g_part[blk][k] = rbuf[k][0] + rbuf[k][1] + rbuf[k][2] + rbuf[k][3];
        }
    }

    // ---------------- fused finalize: last block reduces all partials ----------------
    __shared__ int isLast;
    if (tx == 0) {
        __threadfence();
        unsigned t = atomicAdd(&g_ctr, 1u);
        isLast = (t == (unsigned)(NBLK - 1)) ? 1 : 0;
    }
    __syncthreads();

    if (isLast) {
        double a0 = 0.0, a1 = 0.0, a2 = 0.0, a3 = 0.0;
        const float4* gp = (const float4*)g_part;
#pragma unroll
        for (int k = 0; k < 8; ++k) {
            float4 v = __ldcg(&gp[tx + k * 128]);
            a0 += (double)v.x; a1 += (double)v.y; a2 += (double)v.z; a3 += (double)v.w;
        }
        int lane = tx & 31, wid = tx >> 5;
#pragma unroll
        for (int off = 16; off; off >>= 1) {
            a0 += __shfl_down_sync(0xffffffffu, a0, off);
            a1 += __shfl_down_sync(0xffffffffu, a1, off);
            a2 += __shfl_down_sync(0xffffffffu, a2, off);
            a3 += __shfl_down_sync(0xffffffffu, a3, off);
        }
        __shared__ double sd[4][4];
        if (lane == 0) { sd[0][wid] = a0; sd[1][wid] = a1; sd[2][wid] = a2; sd[3][wid] = a3; }
        __syncthreads();
        if (tx == 0) {
            double t0 = sd[0][0] + sd[0][1] + sd[0][2] + sd[0][3];
            double t1 = sd[1][0] + sd[1][1] + sd[1][2] + sd[1][3];
            double t2 = sd[2][0] + sd[2][1] + sd[2][2] + sd[2][3];
            double t3 = sd[3][0] + sd[3][1] + sd[3][2] + sd[3][3];
            const double NI = 256.0 * 126.0 * 126.0;
            double loss_base = t0 / 300000.0;
            double loss_bc   = t1 / (256.0 * 988.0);
            double loss_cont = (t2 / NI) / 1e-5;
            double loss_ns   = (t3 / (NI * 2.0)) / 0.01;
            double A_LOSS = 1.0 - 0.3 - 0.3 - 0.3;
            out[0] = (float)(A_LOSS * loss_base + 0.3 * loss_cont + 0.3 * loss_ns + 0.3 * loss_bc);
            g_ctr = 0u;   // reset for next launch / graph replay
        }
    }
}

extern "C" void kernel_launch(void* const* d_in, const int* in_sizes, int n_in,
                              void* d_out, int out_size) {
    const int SMALL = 256 * 128 * 128;
    int idx_in = 0;
    for (int i = 0; i < n_in; ++i)
        if (in_sizes[i] == SMALL) { idx_in = i; break; }
    const float* inp = (const float*)d_in[idx_in];
    const float* big[2];
    int nb = 0;
    for (int i = 0; i < n_in && nb < 2; ++i)
        if (i != idx_in) big[nb++] = (const float*)d_in[i];
    const float* outp = big[0];
    const float* tgt  = big[1];

    physics_kernel<<<NBLK, 128>>>(inp, outp, tgt, (float*)d_out);
}

// round 3
// speedup vs baseline: 1.8261x; 1.3043x over previous
#include <cuda_runtime.h>

#define CHUNKS 8
#define ROWS_PER 16
#define NBLK (256 * CHUNKS)   // 2048

__device__ float g_part[NBLK][4];
__device__ unsigned int g_ctr;

// 1st+2nd derivative, torch.gradient semantics on a cropped 126-array.
// cls: 0=left edge, 1=left+1, 2=interior, 3=right-1, 4=right edge
__device__ __forceinline__ void d12(float fm2, float fm1, float f0, float fp1, float fp2,
                                    int cls, float inv_h, float inv_2h, float c2,
                                    float& d1, float& d2) {
    if (cls == 2)      { d1 = (fp1 - fm1) * inv_2h; d2 = (fp2 - 2.f * f0 + fm2) * c2; }
    else if (cls == 0) { d1 = (fp1 - f0) * inv_h;
                         d2 = ((fp2 - f0) * inv_2h - (fp1 - f0) * inv_h) * inv_h; }
    else if (cls == 1) { d1 = (fp1 - fm1) * inv_2h;
                         d2 = ((fp2 - f0) * inv_2h - (f0 - fm1) * inv_h) * inv_2h; }
    else if (cls == 3) { d1 = (fp1 - fm1) * inv_2h;
                         d2 = ((fp1 - f0) * inv_h - (f0 - fm2) * inv_2h) * inv_2h; }
    else               { d1 = (f0 - fm1) * inv_h;
                         d2 = ((f0 - fm1) * inv_h - (f0 - fm2) * inv_2h) * inv_h; }
}

__global__ __launch_bounds__(128) void physics_kernel(
    const float* __restrict__ inp,   // (256,1,128,128)
    const float* __restrict__ outp,  // (256,3,128,128)
    const float* __restrict__ tgt,   // (256,3,128,128)
    float* __restrict__ out)
{
    const int blk   = blockIdx.x;
    const int b     = blk >> 3;
    const int chunk = blk & 7;
    const int tx    = threadIdx.x;
    const int y0    = chunk * ROWS_PER;

    constexpr float INV_SX  = 127.0f / 1.2f;
    constexpr float INV_2SX = 127.0f / 2.4f;
    constexpr float INV_SY  = 127.0f / 0.8f;
    constexpr float INV_2SY = 127.0f / 1.6f;
    constexpr float C2X = INV_2SX * INV_2SX;
    constexpr float C2Y = INV_2SY * INV_2SY;

    const float* Ob = outp + b * 49152;
    const float* Tb = tgt  + b * 49152;
    const float* Ib = inp  + b * 16384;

    float s_base = 0.f, s_bc = 0.f, s_cont = 0.f, s_ns = 0.f;

    // ---------------- base loss + boundary loss (float4, 16 rows) ----------------
    {
        const float4* O4 = (const float4*)Ob;
        const float4* T4 = (const float4*)Tb;
        const int col4 = tx & 31;
        const int ry   = tx >> 5;
#pragma unroll
        for (int it = 0; it < 4; ++it) {
            int y   = y0 + it * 4 + ry;
            int idx = y * 32 + col4;
            float4 o0 = O4[idx], o1 = O4[4096 + idx], o2 = O4[8192 + idx];
            float4 t0 = T4[idx], t1 = T4[4096 + idx], t2 = T4[8192 + idx];
            float d;
            d = o0.x - t0.x; s_base += d * d;  d = o0.y - t0.y; s_base += d * d;
            d = o0.z - t0.z; s_base += d * d;  d = o0.w - t0.w; s_base += d * d;
            d = o1.x - t1.x; s_base += d * d;  d = o1.y - t1.y; s_base += d * d;
            d = o1.z - t1.z; s_base += d * d;  d = o1.w - t1.w; s_base += d * d;
            d = o2.x - t2.x; s_base += d * d;  d = o2.y - t2.y; s_base += d * d;
            d = o2.z - t2.z; s_base += d * d;  d = o2.w - t2.w; s_base += d * d;

            bool midrow = (y >= 55) && (y < 73);
            if (y == 0 || y == 127)
                s_bc += o1.x * o1.x + o1.y * o1.y + o1.z * o1.z + o1.w * o1.w
                      + o2.x * o2.x + o2.y * o2.y + o2.z * o2.z + o2.w * o2.w;
            if (col4 == 0) {
                if (midrow) { float e = o1.x - 0.01f; s_bc += e * e; }
                else        s_bc += o1.x * o1.x + o2.x * o2.x;
            }
            if (col4 == 31) {
                if (midrow) s_bc += o0.w * o0.w;
                else        s_bc += o1.w * o1.w + o2.w * o2.w;
            }
        }
    }

    // ---------------- PDE on cropped 126x126 interior ----------------
    // Cropped coords (j,i) map to global (j+1, i+1).
    __shared__ float2 suv[4][128];   // center-row x-neighbors of u,v (ring depth 4)
    __shared__ float  sp [3][128];   // center-row x-neighbors of p   (ring depth 3)

    const float* U = Ob + 16384 + 129;
    const float* V = Ob + 32768 + 129;
    const float* P = Ob + 129;
    const float* A = Ib + 129;

    const int jlo = max(y0 - 1, 0);
    const int jhi = min(y0 + ROWS_PER - 1, 126);
    const bool act = (tx < 126);

    // per-thread x-index math (hoisted)
    const int i   = tx;
    const int im2 = max(i - 2, 0),  im1 = max(i - 1, 0);
    const int ip1 = min(i + 1, 125), ip2 = min(i + 2, 125);
    const int cls_x = (i >= 2 && i <= 123) ? 2 : (i == 0 ? 0 : (i == 1 ? 1 : (i == 124 ? 3 : 4)));

    // register windows
    float2 uv_m2 = make_float2(0.f, 0.f), uv_m1 = uv_m2, uv_c = uv_m2, uv_p1 = uv_m2, uv_p2 = uv_m2;
    float  p_m1 = 0.f, p_c = 0.f, p_p1 = 0.f;

    if (act) {
        // uv rows jlo-2..jlo+2 (clamped to >=0; missing ones unused by edge formulas)
        if (jlo >= 2) uv_m2 = make_float2(U[(jlo - 2) * 128 + i], V[(jlo - 2) * 128 + i]);
        if (jlo >= 1) uv_m1 = make_float2(U[(jlo - 1) * 128 + i], V[(jlo - 1) * 128 + i]);
        uv_c  = make_float2(U[jlo * 128 + i],       V[jlo * 128 + i]);
        uv_p1 = make_float2(U[(jlo + 1) * 128 + i], V[(jlo + 1) * 128 + i]);
        uv_p2 = make_float2(U[(jlo + 2) * 128 + i], V[(jlo + 2) * 128 + i]);
        if (jlo >= 1) p_m1 = P[(jlo - 1) * 128 + i];
        p_c  = P[jlo * 128 + i];
        p_p1 = P[(jlo + 1) * 128 + i];
        // pre-store center rows jlo, jlo+1 (uv) and jlo (p) into the rings
        suv[jlo & 3][tx]       = uv_c;
        suv[(jlo + 1) & 3][tx] = uv_p1;
        sp[jlo % 3][tx]        = p_c;
    }

    int kc  = jlo & 3;                    // uv slot of row j
    int kpc = jlo % 3;                    // p slot of row j
    int kpw = (jlo + 1) % 3;              // p slot of row j+1 (write)
    __syncthreads();

    for (int j = jlo; j < jhi; ++j) {
        // stage rows j+2 (uv) and j+1 (p) into the rings (values already in regs)
        if (act) {
            suv[(kc + 2) & 3][tx] = uv_p2;
            sp[kpw][tx]           = p_p1;
        }
        __syncthreads();

        float2 nuv = make_float2(0.f, 0.f);
        float  np  = 0.f, alpha = 0.f;
        if (act) {
            // prefetch next rows early (hide latency under compute)
            if (j + 3 <= 125) nuv = make_float2(U[(j + 3) * 128 + i], V[(j + 3) * 128 + i]);
            if (j + 2 <= 125) np = P[(j + 2) * 128 + i];
            alpha = A[j * 128 + i];

            const float2* cs = suv[kc];
            const float*  ps = sp[kpc];

            // x-direction (smem neighbors, register center)
            float2 xm2 = cs[im2], xm1 = cs[im1], xp1 = cs[ip1], xp2 = cs[ip2];
            float du_dx, du_dxx, dv_dx, dv_dxx;
            d12(xm2.x, xm1.x, uv_c.x, xp1.x, xp2.x, cls_x, INV_SX, INV_2SX, C2X, du_dx, du_dxx);
            d12(xm2.y, xm1.y, uv_c.y, xp1.y, xp2.y, cls_x, INV_SX, INV_2SX, C2X, dv_dx, dv_dxx);

            float pxm = ps[im1], pxp = ps[ip1];
            float dp_dx = (i == 0)   ? (pxp - p_c) * INV_SX
                        : (i == 125) ? (p_c - pxm) * INV_SX
                                     : (pxp - pxm) * INV_2SX;

            // y-direction (pure registers)
            int cls_y = (j >= 2 && j <= 123) ? 2 : (j == 0 ? 0 : (j == 1 ? 1 : (j == 124 ? 3 : 4)));
            float du_dy, du_dyy, dv_dy, dv_dyy;
            d12(uv_m2.x, uv_m1.x, uv_c.x, uv_p1.x, uv_p2.x, cls_y, INV_SY, INV_2SY, C2Y, du_dy, du_dyy);
            d12(uv_m2.y, uv_m1.y, uv_c.y, uv_p1.y, uv_p2.y, cls_y, INV_SY, INV_2SY, C2Y, dv_dy, dv_dyy);

            float dp_dy = (j == 0)   ? (p_p1 - p_c) * INV_SY
                        : (j == 125) ? (p_c - p_m1) * INV_SY
                                     : (p_p1 - p_m1) * INV_2SY;

            float div = du_dx + dv_dy;
            s_cont += div * div;
            float xres = uv_c.x * du_dx + uv_c.y * du_dy + dp_dx - (du_dxx + du_dyy) + alpha * uv_c.x;
            float yres = uv_c.x * dv_dx + uv_c.y * dv_dy + dp_dy - (dv_dxx + dv_dyy) + alpha * uv_c.y;
            s_ns += xres * xres + yres * yres;

            // rotate register windows
            uv_m2 = uv_m1; uv_m1 = uv_c; uv_c = uv_p1; uv_p1 = uv_p2; uv_p2 = nuv;
            p_m1 = p_c; p_c = p_p1; p_p1 = np;
        }

        // rotate ring counters (uniform)
        kc  = (kc + 1) & 3;
        kpc = (kpc == 2) ? 0 : kpc + 1;
        kpw = (kpw == 2) ? 0 : kpw + 1;
    }

    // ---------------- block reduction -> g_part ----------------
    {
        float vals[4] = {s_base, s_bc, s_cont, s_ns};
        __shared__ float rbuf[4][4];
        int lane = tx & 31, wid = tx >> 5;
#pragma unroll
        for (int k = 0; k < 4; ++k) {
            float v = vals[k];
#pragma unroll
            for (int off = 16; off; off >>= 1) v += __shfl_down_sync(0xffffffffu, v, off);
            if (lane == 0) rbuf[k][wid] = v;
        }
        __syncthreads();
        if (tx == 0) {
#pragma unroll
            for (int k = 0; k < 4; ++k)
                g_part[blk][k] = rbuf[k][0] + rbuf[k][1] + rbuf[k][2] + rbuf[k][3];
        }
    }

    // ---------------- fused finalize: last block reduces all partials ----------------
    __shared__ int isLast;
    if (tx == 0) {
        __threadfence();
        unsigned t = atomicAdd(&g_ctr, 1u);
        isLast = (t == (unsigned)(NBLK - 1)) ? 1 : 0;
    }
    __syncthreads();

    if (isLast) {
        double a0 = 0.0, a1 = 0.0, a2 = 0.0, a3 = 0.0;
        const float4* gp = (const float4*)g_part;
#pragma unroll
        for (int k = 0; k < NBLK / 128; ++k) {
            float4 v = __ldcg(&gp[tx + k * 128]);
            a0 += (double)v.x; a1 += (double)v.y; a2 += (double)v.z; a3 += (double)v.w;
        }
        int lane = tx & 31, wid = tx >> 5;
#pragma unroll
        for (int off = 16; off; off >>= 1) {
            a0 += __shfl_down_sync(0xffffffffu, a0, off);
            a1 += __shfl_down_sync(0xffffffffu, a1, off);
            a2 += __shfl_down_sync(0xffffffffu, a2, off);
            a3 += __shfl_down_sync(0xffffffffu, a3, off);
        }
        __shared__ double sd[4][4];
        if (lane == 0) { sd[0][wid] = a0; sd[1][wid] = a1; sd[2][wid] = a2; sd[3][wid] = a3; }
        __syncthreads();
        if (tx == 0) {
            double t0 = sd[0][0] + sd[0][1] + sd[0][2] + sd[0][3];
            double t1 = sd[1][0] + sd[1][1] + sd[1][2] + sd[1][3];
            double t2 = sd[2][0] + sd[2][1] + sd[2][2] + sd[2][3];
            double t3 = sd[3][0] + sd[3][1] + sd[3][2] + sd[3][3];
            const double NI = 256.0 * 126.0 * 126.0;
            double loss_base = t0 / 300000.0;
            double loss_bc   = t1 / (256.0 * 988.0);
            double loss_cont = (t2 / NI) / 1e-5;
            double loss_ns   = (t3 / (NI * 2.0)) / 0.01;
            double A_LOSS = 1.0 - 0.3 - 0.3 - 0.3;
            out[0] = (float)(A_LOSS * loss_base + 0.3 * loss_cont + 0.3 * loss_ns + 0.3 * loss_bc);
            g_ctr = 0u;   // reset for graph replay
        }
    }
}

extern "C" void kernel_launch(void* const* d_in, const int* in_sizes, int n_in,
                              void* d_out, int out_size) {
    const int SMALL = 256 * 128 * 128;
    int idx_in = 0;
    for (int i = 0; i < n_in; ++i)
        if (in_sizes[i] == SMALL) { idx_in = i; break; }
    const float* inp = (const float*)d_in[idx_in];
    const float* big[2];
    int nb = 0;
    for (int i = 0; i < n_in && nb < 2; ++i)
        if (i != idx_in) big[nb++] = (const float*)d_in[i];
    const float* outp = big[0];
    const float* tgt  = big[1];

    physics_kernel<<<NBLK, 128>>>(inp, outp, tgt, (float*)d_out);
}